// round 1
// baseline (speedup 1.0000x reference)
#include <cuda_runtime.h>

#define RADIUS_F 5.0f
#define ECONV_F  14.399645f
#define MAX_ATOMS_COMB 262144

// Fused (charge, mol_index) per atom so the per-pair "first" gather is one 8B load.
__device__ float2 g_comb[MAX_ATOMS_COMB];

__global__ void prep_kernel(const float* __restrict__ charges,
                            const int*   __restrict__ mol_index,
                            int n_atoms, int use_comb,
                            float* __restrict__ out, int n_mol)
{
    int i = blockIdx.x * blockDim.x + threadIdx.x;
    if (use_comb && i < n_atoms) {
        float2 c;
        c.x = charges[i];
        c.y = __int_as_float(mol_index[i]);
        g_comb[i] = c;
    }
    if (i < n_mol) out[i] = 0.0f;
}

template <bool USE_COMB>
__device__ __forceinline__ void accum_pair(
    float r, int fi, int si,
    const float* __restrict__ charges,
    const int*   __restrict__ mol_index,
    float* __restrict__ bins)
{
    if (r < RADIUS_F) {
        float qi; int mol;
        if (USE_COMB) {
            float2 c = g_comb[fi];
            qi  = c.x;
            mol = __float_as_int(c.y);
        } else {
            qi  = __ldg(charges + fi);
            mol = __ldg(mol_index + fi);
        }
        float qj  = __ldg(charges + si);
        float scr = 0.5f * (1.0f + cospif(r * (1.0f / RADIUS_F)));
        float e   = qi * qj * __fdividef(scr, r);
        atomicAdd(bins + mol, e);
    }
}

template <bool USE_COMB>
__global__ void __launch_bounds__(1024, 2)
pair_kernel(const float* __restrict__ pair_dist,
            const int*   __restrict__ pair_first,
            const int*   __restrict__ pair_second,
            const float* __restrict__ charges,
            const int*   __restrict__ mol_index,
            float* __restrict__ out,
            int n_pairs, int n_mol)
{
    extern __shared__ float bins[];
    for (int b = threadIdx.x; b < n_mol; b += blockDim.x) bins[b] = 0.0f;
    __syncthreads();

    const int gtid   = blockIdx.x * blockDim.x + threadIdx.x;
    const int stride = gridDim.x * blockDim.x;
    const int n4     = n_pairs >> 2;

    const float4* __restrict__ pd4 = (const float4*)pair_dist;
    const int4*   __restrict__ pf4 = (const int4*)pair_first;
    const int4*   __restrict__ ps4 = (const int4*)pair_second;

    for (int i = gtid; i < n4; i += stride) {
        float4 d = pd4[i];
        int4   f = pf4[i];
        int4   s = ps4[i];
        accum_pair<USE_COMB>(d.x, f.x, s.x, charges, mol_index, bins);
        accum_pair<USE_COMB>(d.y, f.y, s.y, charges, mol_index, bins);
        accum_pair<USE_COMB>(d.z, f.z, s.z, charges, mol_index, bins);
        accum_pair<USE_COMB>(d.w, f.w, s.w, charges, mol_index, bins);
    }
    // tail (n_pairs not divisible by 4)
    for (int i = (n4 << 2) + gtid; i < n_pairs; i += stride) {
        accum_pair<USE_COMB>(pair_dist[i], pair_first[i], pair_second[i],
                             charges, mol_index, bins);
    }

    __syncthreads();
    for (int b = threadIdx.x; b < n_mol; b += blockDim.x) {
        float v = bins[b];
        if (v != 0.0f) atomicAdd(out + b, 0.5f * ECONV_F * v);
    }
}

// Fallback if n_mol is too large for shared-memory privatization.
__global__ void pair_kernel_global(const float* __restrict__ pair_dist,
                                   const int*   __restrict__ pair_first,
                                   const int*   __restrict__ pair_second,
                                   const float* __restrict__ charges,
                                   const int*   __restrict__ mol_index,
                                   float* __restrict__ out, int n_pairs)
{
    const int gtid   = blockIdx.x * blockDim.x + threadIdx.x;
    const int stride = gridDim.x * blockDim.x;
    for (int i = gtid; i < n_pairs; i += stride) {
        float r = pair_dist[i];
        if (r < RADIUS_F) {
            int   fi  = pair_first[i];
            float qi  = __ldg(charges + fi);
            int   mol = __ldg(mol_index + fi);
            float qj  = __ldg(charges + pair_second[i]);
            float scr = 0.5f * (1.0f + cospif(r * (1.0f / RADIUS_F)));
            float e   = 0.5f * ECONV_F * qi * qj * __fdividef(scr, r);
            atomicAdd(out + mol, e);
        }
    }
}

extern "C" void kernel_launch(void* const* d_in, const int* in_sizes, int n_in,
                              void* d_out, int out_size)
{
    const float* charges     = (const float*)d_in[0];
    const float* pair_dist   = (const float*)d_in[1];
    const int*   pair_first  = (const int*)d_in[2];
    const int*   pair_second = (const int*)d_in[3];
    const int*   mol_index   = (const int*)d_in[4];

    int n_atoms = in_sizes[0];
    int n_pairs = in_sizes[1];
    int n_mol   = out_size;
    float* out  = (float*)d_out;

    int use_comb = (n_atoms <= MAX_ATOMS_COMB) ? 1 : 0;

    int prep_n = n_atoms > n_mol ? n_atoms : n_mol;
    prep_kernel<<<(prep_n + 255) / 256, 256>>>(charges, mol_index, n_atoms,
                                               use_comb, out, n_mol);

    const int threads = 1024;
    const int blocks  = 296;  // 2 CTAs/SM on 148 SMs
    size_t smem = (size_t)n_mol * sizeof(float);

    if (smem <= 48 * 1024) {
        if (use_comb)
            pair_kernel<true><<<blocks, threads, smem>>>(
                pair_dist, pair_first, pair_second, charges, mol_index,
                out, n_pairs, n_mol);
        else
            pair_kernel<false><<<blocks, threads, smem>>>(
                pair_dist, pair_first, pair_second, charges, mol_index,
                out, n_pairs, n_mol);
    } else {
        pair_kernel_global<<<blocks, threads>>>(
            pair_dist, pair_first, pair_second, charges, mol_index,
            out, n_pairs);
    }
}